// round 1
// baseline (speedup 1.0000x reference)
#include <cuda_runtime.h>
#include <math.h>

#define B_ 8
#define T_ 512
#define J_ 26
#define D_ 256
#define H_ 8
#define DH_ 32
#define HID_ 1024
#define NTOK 106496            // B*T*J
#define EPSF 1e-6f

// ---------------- scratch (static device .bss; no allocations) ----------------
__device__ float g_t  [(size_t)NTOK * D_];     // t / attn-out / f  (reused)
__device__ float g_q  [(size_t)NTOK * D_];     // pq / o
__device__ float g_k  [(size_t)NTOK * D_];     // pk / u2
__device__ float g_v  [(size_t)NTOK * D_];     // v
__device__ float g_hid[(size_t)NTOK * HID_];   // FFN hidden
__device__ float g_kv [(size_t)B_ * J_ * H_ * DH_ * DH_];
__device__ float g_ks [(size_t)B_ * J_ * H_ * DH_];

// ---------------- block reduction (256 threads) ----------------
__device__ __forceinline__ float block_reduce_sum(float v, float* sbuf) {
    int lane = threadIdx.x & 31, w = threadIdx.x >> 5;
    #pragma unroll
    for (int o = 16; o; o >>= 1) v += __shfl_down_sync(0xffffffffu, v, o);
    if (lane == 0) sbuf[w] = v;
    __syncthreads();
    float r = (threadIdx.x < 8) ? sbuf[threadIdx.x] : 0.f;
    if (w == 0) {
        r += __shfl_down_sync(0xffffffffu, r, 4);
        r += __shfl_down_sync(0xffffffffu, r, 2);
        r += __shfl_down_sync(0xffffffffu, r, 1);
        if (lane == 0) sbuf[0] = r;
    }
    __syncthreads();
    float res = sbuf[0];
    __syncthreads();           // allow sbuf reuse by next call
    return res;
}

// ---------------- K1: t = layernorm(logmap0(x), g1, b1) ----------------
// (expmap0 -> logmap0 round-trip in the reference is the identity; skipped)
__global__ void pre_kernel(const float* __restrict__ x,
                           const float* __restrict__ g1,
                           const float* __restrict__ b1,
                           float* __restrict__ t_out) {
    __shared__ float sbuf[32];
    int row = blockIdx.x;
    int i = threadIdx.x;
    const float* xr = x + (size_t)row * (D_ + 1);
    float xi = xr[1 + i];
    float ss = block_reduce_sum(xi * xi, sbuf);
    float n  = fmaxf(sqrtf(ss), EPSF);
    float x0 = fmaxf(xr[0], 1.0f + 1e-7f);
    float u  = acoshf(x0) * xi / n;
    float s1 = block_reduce_sum(u, sbuf);
    float s2 = block_reduce_sum(u * u, sbuf);
    float mean = s1 * (1.f / D_);
    float var  = s2 * (1.f / D_) - mean * mean;
    float r    = rsqrtf(var + 1e-5f);
    t_out[(size_t)row * D_ + i] = (u - mean) * r * g1[i] + b1[i];
}

// ---------------- SGEMM 128x128x8, 256 threads, 8x8 per thread ----------------
// C[N,M] = act(A[N,K] @ W[K,M] + bias[M]); N,M multiples of 128, K multiple of 8
// ACT: 0 none, 1 elu(x)+1, 2 gelu(tanh)
template<int ACT>
__global__ __launch_bounds__(256) void sgemm_kernel(
    const float* __restrict__ A, const float* __restrict__ W,
    const float* __restrict__ bias, float* __restrict__ C,
    int K, int M)
{
    __shared__ float As[8][128];
    __shared__ float Bs[8][128];
    int bm = blockIdx.y, bn = blockIdx.x;
    int tid = threadIdx.x;
    int tx = tid & 15, ty = tid >> 4;

    const float* Ab = A + (size_t)bm * 128 * K;
    const float* Bb = W + (size_t)bn * 128;

    int arow = tid >> 1;            // 0..127
    int acol = (tid & 1) * 4;       // 0 or 4
    int brow = tid >> 5;            // 0..7
    int bcol = (tid & 31) * 4;      // 0..124

    float acc[8][8];
    #pragma unroll
    for (int i = 0; i < 8; i++)
        #pragma unroll
        for (int j = 0; j < 8; j++) acc[i][j] = 0.f;

    for (int k0 = 0; k0 < K; k0 += 8) {
        float4 a4 = *(const float4*)(Ab + (size_t)arow * K + k0 + acol);
        float4 b4 = *(const float4*)(Bb + (size_t)(k0 + brow) * M + bcol);
        As[acol + 0][arow] = a4.x;
        As[acol + 1][arow] = a4.y;
        As[acol + 2][arow] = a4.z;
        As[acol + 3][arow] = a4.w;
        *(float4*)&Bs[brow][bcol] = b4;
        __syncthreads();
        #pragma unroll
        for (int kk = 0; kk < 8; kk++) {
            float af[8], bf[8];
            *(float4*)(af)     = *(const float4*)&As[kk][ty * 8];
            *(float4*)(af + 4) = *(const float4*)&As[kk][ty * 8 + 4];
            *(float4*)(bf)     = *(const float4*)&Bs[kk][tx * 8];
            *(float4*)(bf + 4) = *(const float4*)&Bs[kk][tx * 8 + 4];
            #pragma unroll
            for (int i = 0; i < 8; i++)
                #pragma unroll
                for (int j = 0; j < 8; j++)
                    acc[i][j] += af[i] * bf[j];
        }
        __syncthreads();
    }

    int crow0 = bm * 128 + ty * 8;
    int ccol0 = bn * 128 + tx * 8;
    float bi[8];
    #pragma unroll
    for (int j = 0; j < 8; j++) bi[j] = bias[ccol0 + j];

    #pragma unroll
    for (int i = 0; i < 8; i++) {
        float v[8];
        #pragma unroll
        for (int j = 0; j < 8; j++) {
            float val = acc[i][j] + bi[j];
            if (ACT == 1) {                      // elu(x)+1
                val = (val > 0.f) ? (val + 1.f) : __expf(val);
            } else if (ACT == 2) {               // gelu (tanh approx, jax default)
                float c = val * val * val;
                val = 0.5f * val * (1.f + tanhf(0.7978845608028654f * (val + 0.044715f * c)));
            }
            v[j] = val;
        }
        float* crow = C + (size_t)(crow0 + i) * M + ccol0;
        *(float4*)(crow)     = *(float4*)(v);
        *(float4*)(crow + 4) = *(float4*)(v + 4);
    }
}

// ---------------- K3: kv[k,d] = sum_t pk[t,k] v[t,d]; ksum[k] = sum_t pk[t,k] ----
__global__ void kv_reduce_kernel(const float* __restrict__ pk,
                                 const float* __restrict__ v,
                                 float* __restrict__ kv,
                                 float* __restrict__ ksum) {
    int bh = blockIdx.x;              // (b*J + j)*H + h
    int h  = bh % H_;
    int bj = bh / H_;
    int j  = bj % J_;
    int b  = bj / J_;
    int tid = threadIdx.x;
    int lane = tid & 31, w = tid >> 5;

    __shared__ float sp[4][32];
    __shared__ float sv[4][32];

    float acc[4] = {0.f, 0.f, 0.f, 0.f};
    float ks = 0.f;

    int tl = tid >> 6;        // 0..3 (which timestep within group)
    int e  = tid & 63;        // 0..63: 0-31 pk, 32-63 v

    for (int t0 = 0; t0 < T_; t0 += 4) {
        int t = t0 + tl;
        size_t base = (((size_t)(b * T_ + t) * J_) + j) * D_ + h * DH_;
        float val = (e < 32) ? pk[base + e] : v[base + e - 32];
        __syncthreads();
        if (e < 32) sp[tl][e] = val; else sv[tl][e - 32] = val;
        __syncthreads();
        #pragma unroll
        for (int tt = 0; tt < 4; tt++) {
            float vv = sv[tt][lane];
            #pragma unroll
            for (int c = 0; c < 4; c++)
                acc[c] += sp[tt][w + c * 8] * vv;
            if (w == 0) ks += sp[tt][lane];
        }
    }

    size_t ob = (size_t)bh * (DH_ * DH_);
    #pragma unroll
    for (int c = 0; c < 4; c++)
        kv[ob + (size_t)(w + c * 8) * 32 + lane] = acc[c];
    if (w == 0) ksum[(size_t)bh * 32 + lane] = ks;
}

// ---------------- K4: y = (pq @ kv) / (pq . ksum + EPS) ----------------
__global__ void attn_apply_kernel(const float* __restrict__ pq,
                                  const float* __restrict__ kv,
                                  const float* __restrict__ ksum,
                                  float* __restrict__ y) {
    int bh = blockIdx.x;
    int h  = bh % H_;
    int bj = bh / H_;
    int j  = bj % J_;
    int b  = bj / J_;
    __shared__ float skv[DH_ * DH_];
    __shared__ float sks[DH_];
    int tid = threadIdx.x;
    for (int i = tid; i < DH_ * DH_; i += 256) skv[i] = kv[(size_t)bh * (DH_ * DH_) + i];
    if (tid < DH_) sks[tid] = ksum[(size_t)bh * DH_ + tid];
    __syncthreads();

    int lane = tid & 31, w = tid >> 5;
    for (int t = w; t < T_; t += 8) {
        size_t base = (((size_t)(b * T_ + t) * J_) + j) * D_ + h * DH_;
        float q = pq[base + lane];
        float den = q * sks[lane];
        #pragma unroll
        for (int o = 16; o; o >>= 1) den += __shfl_xor_sync(0xffffffffu, den, o);
        float num = 0.f;
        #pragma unroll
        for (int k = 0; k < 32; k++)
            num += __shfl_sync(0xffffffffu, q, k) * skv[k * 32 + lane];
        y[base + lane] = num / (den + EPSF);
    }
}

// ---------------- K5: z=expmap0(o); h=lorentz_residual(x,z); u2=LN(logmap0(h)) ---
__global__ void resid_kernel(const float* __restrict__ x,
                             const float* __restrict__ o_in,
                             const float* __restrict__ g2,
                             const float* __restrict__ b2,
                             float* __restrict__ u2_out) {
    __shared__ float sbuf[32];
    int row = blockIdx.x;
    int i = threadIdx.x;
    const float* xr = x + (size_t)row * (D_ + 1);
    float o = o_in[(size_t)row * D_ + i];
    float so = block_reduce_sum(o * o, sbuf);
    float n  = fmaxf(sqrtf(so), EPSF);
    float z  = sinhf(n) * o / n;
    float m  = xr[1 + i] + z;
    float sm = block_reduce_sum(m * m, sbuf);
    float m0 = xr[0] + coshf(n);
    float mink = -m0 * m0 + sm;
    float inv  = rsqrtf(fmaxf(-mink, EPSF));
    float h0   = m0 * inv;
    float hs   = m * inv;
    float hn   = fmaxf(sqrtf(sm) * inv, EPSF);
    float u    = acoshf(fmaxf(h0, 1.0f + 1e-7f)) * hs / hn;
    float s1 = block_reduce_sum(u, sbuf);
    float s2 = block_reduce_sum(u * u, sbuf);
    float mean = s1 * (1.f / D_);
    float var  = s2 * (1.f / D_) - mean * mean;
    u2_out[(size_t)row * D_ + i] = (u - mean) * rsqrtf(var + 1e-5f) * g2[i] + b2[i];
}

// ---------------- K6: out = expmap0(f) ----------------
__global__ void final_kernel(const float* __restrict__ f_in,
                             float* __restrict__ out) {
    __shared__ float sbuf[32];
    int row = blockIdx.x;
    int i = threadIdx.x;
    float f = f_in[(size_t)row * D_ + i];
    float ss = block_reduce_sum(f * f, sbuf);
    float n  = fmaxf(sqrtf(ss), EPSF);
    float* orow = out + (size_t)row * (D_ + 1);
    orow[1 + i] = sinhf(n) * f / n;
    if (i == 0) orow[0] = coshf(n);
}

// ---------------- launch ----------------
extern "C" void kernel_launch(void* const* d_in, const int* /*in_sizes*/, int /*n_in*/,
                              void* d_out, int /*out_size*/) {
    const float* x     = (const float*)d_in[0];
    const float* g1    = (const float*)d_in[1];
    const float* beta1 = (const float*)d_in[2];
    const float* Wq    = (const float*)d_in[3];
    const float* Wk    = (const float*)d_in[4];
    const float* Wv    = (const float*)d_in[5];
    const float* Wo    = (const float*)d_in[6];
    const float* bq    = (const float*)d_in[7];
    const float* bk    = (const float*)d_in[8];
    const float* bv    = (const float*)d_in[9];
    const float* bo    = (const float*)d_in[10];
    const float* g2    = (const float*)d_in[11];
    const float* beta2 = (const float*)d_in[12];
    const float* W1    = (const float*)d_in[13];
    const float* bf1   = (const float*)d_in[14];
    const float* W2    = (const float*)d_in[15];
    const float* bf2   = (const float*)d_in[16];
    float* out = (float*)d_out;

    float *t_, *q_, *k_, *v_, *hid_, *kv_, *ks_;
    cudaGetSymbolAddress((void**)&t_,   g_t);
    cudaGetSymbolAddress((void**)&q_,   g_q);
    cudaGetSymbolAddress((void**)&k_,   g_k);
    cudaGetSymbolAddress((void**)&v_,   g_v);
    cudaGetSymbolAddress((void**)&hid_, g_hid);
    cudaGetSymbolAddress((void**)&kv_,  g_kv);
    cudaGetSymbolAddress((void**)&ks_,  g_ks);

    // 1. pre: x -> t
    pre_kernel<<<NTOK, 256>>>(x, g1, beta1, t_);

    // 2. QKV projections with fused activations
    dim3 gD(D_ / 128, NTOK / 128);     // (2, 832)
    sgemm_kernel<1><<<gD, 256>>>(t_, Wq, bq, q_, D_, D_);   // pq = elu(q)+1
    sgemm_kernel<1><<<gD, 256>>>(t_, Wk, bk, k_, D_, D_);   // pk = elu(k)+1
    sgemm_kernel<0><<<gD, 256>>>(t_, Wv, bv, v_, D_, D_);   // v

    // 3. linear attention
    kv_reduce_kernel<<<B_ * J_ * H_, 256>>>(k_, v_, kv_, ks_);
    attn_apply_kernel<<<B_ * J_ * H_, 256>>>(q_, kv_, ks_, t_);   // y -> t_

    // 4. output projection: o = y @ Wo + bo  -> q_
    sgemm_kernel<0><<<gD, 256>>>(t_, Wo, bo, q_, D_, D_);

    // 5. Lorentz residual + LN2 -> k_ (u2)
    resid_kernel<<<NTOK, 256>>>(x, q_, g2, beta2, k_);

    // 6. FFN
    dim3 gH(HID_ / 128, NTOK / 128);   // (8, 832)
    sgemm_kernel<2><<<gH, 256>>>(k_, W1, bf1, hid_, D_, HID_);   // gelu
    sgemm_kernel<0><<<gD, 256>>>(hid_, W2, bf2, t_, HID_, D_);   // f -> t_

    // 7. final expmap0 -> out
    final_kernel<<<NTOK, 256>>>(t_, out);
}

// round 4
// speedup vs baseline: 1.8963x; 1.8963x over previous
#include <cuda_runtime.h>
#include <cuda_bf16.h>
#include <math.h>
#include <stdint.h>

#define B_ 8
#define T_ 512
#define J_ 26
#define D_ 256
#define H_ 8
#define DH_ 32
#define HID_ 1024
#define NTOK 106496            // B*T*J  (= 832 * 128 exactly)
#define EPSF 1e-6f

// ================= PTX helpers (base ISA only: sm_80+ features) =================
__device__ __forceinline__ uint32_t smem_u32(const void* p) {
    uint32_t a;
    asm("{ .reg .u64 t; cvta.to.shared.u64 t, %1; cvt.u32.u64 %0, t; }" : "=r"(a) : "l"(p));
    return a;
}
#define CP_ASYNC16(dst, src) \
    asm volatile("cp.async.cg.shared.global [%0], [%1], 16;" :: "r"(dst), "l"(src) : "memory")
#define CP_COMMIT() asm volatile("cp.async.commit_group;" ::: "memory")
#define CP_WAIT(n)  asm volatile("cp.async.wait_group %0;" :: "n"(n) : "memory")

#define LDSM4(r0, r1, r2, r3, addr) \
    asm volatile("ldmatrix.sync.aligned.m8n8.x4.shared.b16 {%0,%1,%2,%3}, [%4];" \
        : "=r"(r0), "=r"(r1), "=r"(r2), "=r"(r3) : "r"(addr))
#define LDSM2(r0, r1, addr) \
    asm volatile("ldmatrix.sync.aligned.m8n8.x2.shared.b16 {%0,%1}, [%2];" \
        : "=r"(r0), "=r"(r1) : "r"(addr))

__device__ __forceinline__ void mma16816(float* c, const uint32_t* a, const uint32_t* b) {
    asm volatile(
        "mma.sync.aligned.m16n8k16.row.col.f32.bf16.bf16.f32 "
        "{%0,%1,%2,%3}, {%4,%5,%6,%7}, {%8,%9}, {%0,%1,%2,%3};"
        : "+f"(c[0]), "+f"(c[1]), "+f"(c[2]), "+f"(c[3])
        : "r"(a[0]), "r"(a[1]), "r"(a[2]), "r"(a[3]), "r"(b[0]), "r"(b[1]));
}

// ================= scratch (static device .bss) =================
__device__ __nv_bfloat16 g_th [(size_t)NTOK * D_];    // t / y / u2  hi
__device__ __nv_bfloat16 g_tl [(size_t)NTOK * D_];    // t / y / u2  lo
__device__ float         g_q  [(size_t)NTOK * D_];    // pq / o / f
__device__ float         g_k  [(size_t)NTOK * D_];    // pk
__device__ float         g_v  [(size_t)NTOK * D_];    // v
__device__ __nv_bfloat16 g_hh [(size_t)NTOK * HID_];  // hid hi
__device__ __nv_bfloat16 g_hl [(size_t)NTOK * HID_];  // hid lo
__device__ float g_kv [(size_t)B_ * J_ * H_ * DH_ * DH_];
__device__ float g_ks [(size_t)B_ * J_ * H_ * DH_];
// transposed bf16 hi/lo weights: Bt[n,k]
__device__ __nv_bfloat16 g_wqh[D_ * D_],   g_wql[D_ * D_];
__device__ __nv_bfloat16 g_wkh[D_ * D_],   g_wkl[D_ * D_];
__device__ __nv_bfloat16 g_wvh[D_ * D_],   g_wvl[D_ * D_];
__device__ __nv_bfloat16 g_woh[D_ * D_],   g_wol[D_ * D_];
__device__ __nv_bfloat16 g_w1h[D_ * HID_], g_w1l[D_ * HID_];
__device__ __nv_bfloat16 g_w2h[HID_ * D_], g_w2l[HID_ * D_];

// ================= small helpers =================
__device__ __forceinline__ float block_reduce_sum(float v, float* sbuf) {
    int lane = threadIdx.x & 31, w = threadIdx.x >> 5;
    #pragma unroll
    for (int o = 16; o; o >>= 1) v += __shfl_down_sync(0xffffffffu, v, o);
    if (lane == 0) sbuf[w] = v;
    __syncthreads();
    float r = (threadIdx.x < 8) ? sbuf[threadIdx.x] : 0.f;
    if (w == 0) {
        r += __shfl_down_sync(0xffffffffu, r, 4);
        r += __shfl_down_sync(0xffffffffu, r, 2);
        r += __shfl_down_sync(0xffffffffu, r, 1);
        if (lane == 0) sbuf[0] = r;
    }
    __syncthreads();
    float res = sbuf[0];
    __syncthreads();
    return res;
}
__device__ __forceinline__ void split_store(__nv_bfloat16* hi, __nv_bfloat16* lo,
                                            size_t idx, float v) {
    __nv_bfloat16 h = __float2bfloat16(v);
    hi[idx] = h;
    lo[idx] = __float2bfloat16(v - __bfloat162float(h));
}

// ============ weight transpose+split: Bt[n,k] = W[k,n] as bf16 hi/lo ============
__global__ void wsplit_kernel(const float* __restrict__ W,
                              __nv_bfloat16* __restrict__ Bh,
                              __nv_bfloat16* __restrict__ Bl, int K, int N) {
    int idx = blockIdx.x * 256 + threadIdx.x;
    if (idx >= K * N) return;
    int k = idx / N, n = idx % N;
    float w = W[idx];
    __nv_bfloat16 h = __float2bfloat16(w);
    Bh[(size_t)n * K + k] = h;
    Bl[(size_t)n * K + k] = __float2bfloat16(w - __bfloat162float(h));
}

// ============ K1: t = layernorm(logmap0(x)) -> bf16 hi/lo ============
// (expmap0 -> logmap0 round-trip in the reference is the identity; skipped)
__global__ void pre_kernel(const float* __restrict__ x,
                           const float* __restrict__ g1,
                           const float* __restrict__ b1,
                           __nv_bfloat16* __restrict__ th,
                           __nv_bfloat16* __restrict__ tl) {
    __shared__ float sbuf[32];
    int row = blockIdx.x, i = threadIdx.x;
    const float* xr = x + (size_t)row * (D_ + 1);
    float xi = xr[1 + i];
    float ss = block_reduce_sum(xi * xi, sbuf);
    float n  = fmaxf(sqrtf(ss), EPSF);
    float x0 = fmaxf(xr[0], 1.0f + 1e-7f);
    float u  = acoshf(x0) * xi / n;
    float s1 = block_reduce_sum(u, sbuf);
    float s2 = block_reduce_sum(u * u, sbuf);
    float mean = s1 * (1.f / D_);
    float var  = s2 * (1.f / D_) - mean * mean;
    float tv = (u - mean) * rsqrtf(var + 1e-5f) * g1[i] + b1[i];
    split_store(th, tl, (size_t)row * D_ + i, tv);
}

// ============ HMMA split-bf16 GEMM (mma.sync.m16n8k16) =================
// C[m,n] = act( sum_k A[m,k] * Bt[n,k] + bias[n] ), 3-pass hi/lo split.
// ACT: 0 none, 1 elu+1, 2 gelu(tanh). OUT: 0 fp32, 1 bf16 hi/lo split.
// Block 128x128, K-tile 32, 8 warps (4 Mrows x 2 Ncols), warp tile 32x64.
#define ROWB 80                       // padded SMEM row stride (bytes) for 64B data
#define TILEB (128 * ROWB)            // 10240 B per tile
#define STAGEB (4 * TILEB)            // Ah, Al, Bh, Bl
#define GEMM_SMEM (2 * STAGEB)        // 81920 B, double buffered

template<int ACT, int OUT>
__global__ __launch_bounds__(256) void gemm_kernel(
    const __nv_bfloat16* __restrict__ Ah, const __nv_bfloat16* __restrict__ Al,
    const __nv_bfloat16* __restrict__ Bh, const __nv_bfloat16* __restrict__ Bl,
    const float* __restrict__ bias,
    float* __restrict__ Cf,
    __nv_bfloat16* __restrict__ Ch, __nv_bfloat16* __restrict__ Cl,
    int K, int NC)
{
    extern __shared__ char smem[];
    const uint32_t sb = smem_u32(smem);
    const int tid  = threadIdx.x;
    const int lane = tid & 31;
    const int w    = tid >> 5;
    const int mBase = blockIdx.y * 128;
    const int nBase = blockIdx.x * 128;
    const int wm = (w & 3) * 32;      // warp M offset in tile
    const int wn = (w >> 2) * 64;     // warp N offset in tile

    const __nv_bfloat16* srcs[4] = {Ah, Al, Bh, Bl};

    auto load_stage = [&](int kt, int s) {
        int k0 = kt * 32;
        uint32_t sOff = sb + s * STAGEB;
        #pragma unroll
        for (int t = 0; t < 4; t++) {
            int rowBase = (t < 2) ? mBase : nBase;
            const __nv_bfloat16* src = srcs[t];
            #pragma unroll
            for (int it = 0; it < 2; it++) {
                int idx = tid + it * 256;        // 0..511
                int r = idx >> 2, c = idx & 3;
                const __nv_bfloat16* g = src + (size_t)(rowBase + r) * K + k0 + c * 8;
                uint32_t d = sOff + t * TILEB + r * ROWB + c * 16;
                CP_ASYNC16(d, g);
            }
        }
    };

    float acc[2][8][4];
    #pragma unroll
    for (int mt = 0; mt < 2; mt++)
        #pragma unroll
        for (int nt = 0; nt < 8; nt++)
            #pragma unroll
            for (int i = 0; i < 4; i++) acc[mt][nt][i] = 0.f;

    const int nkt = K >> 5;
    load_stage(0, 0);
    CP_COMMIT();

    // ldmatrix per-thread address pieces
    const int aRow = lane & 15;             // row within 16
    const int aSel = lane >> 4;             // 16B half (k0-7 / k8-15)
    const int bRow = lane & 7;
    const int bSel = (lane >> 3) & 1;

    for (int kt = 0; kt < nkt; kt++) {
        if (kt + 1 < nkt) { load_stage(kt + 1, (kt + 1) & 1); CP_COMMIT(); CP_WAIT(1); }
        else              { CP_WAIT(0); }
        __syncthreads();

        uint32_t base = sb + (kt & 1) * STAGEB;
        uint32_t aHb = base;                 // Ah tile
        uint32_t aLb = base + TILEB;         // Al tile
        uint32_t bHb = base + 2 * TILEB;     // Bh tile
        uint32_t bLb = base + 3 * TILEB;     // Bl tile

        #pragma unroll
        for (int kk = 0; kk < 2; kk++) {
            // B fragments: 8 n-tiles x (hi, lo)
            uint32_t bF[2][8][2];
            #pragma unroll
            for (int nt = 0; nt < 8; nt++) {
                uint32_t off = (wn + nt * 8 + bRow) * ROWB + (2 * kk + bSel) * 16;
                LDSM2(bF[0][nt][0], bF[0][nt][1], bHb + off);
                LDSM2(bF[1][nt][0], bF[1][nt][1], bLb + off);
            }
            #pragma unroll
            for (int mt = 0; mt < 2; mt++) {
                uint32_t aH[4], aL[4];
                uint32_t off = (wm + mt * 16 + aRow) * ROWB + (2 * kk + aSel) * 16;
                LDSM4(aH[0], aH[1], aH[2], aH[3], aHb + off);
                LDSM4(aL[0], aL[1], aL[2], aL[3], aLb + off);
                #pragma unroll
                for (int nt = 0; nt < 8; nt++) {
                    mma16816(acc[mt][nt], aH, bF[0][nt]);   // Ah * Bh
                    mma16816(acc[mt][nt], aL, bF[0][nt]);   // Al * Bh
                    mma16816(acc[mt][nt], aH, bF[1][nt]);   // Ah * Bl
                }
            }
        }
        __syncthreads();
    }

    // ---------------- epilogue ----------------
    const int gid = lane >> 2;               // 0..7 (row in 8-block)
    const int tig = lane & 3;                // 0..3 (col pair)
    #pragma unroll
    for (int mt = 0; mt < 2; mt++) {
        #pragma unroll
        for (int nt = 0; nt < 8; nt++) {
            int col = nBase + wn + nt * 8 + tig * 2;
            float b0 = bias[col], b1 = bias[col + 1];
            #pragma unroll
            for (int half = 0; half < 2; half++) {
                int row = mBase + wm + mt * 16 + gid + half * 8;
                float v0 = acc[mt][nt][half * 2 + 0] + b0;
                float v1 = acc[mt][nt][half * 2 + 1] + b1;
                if (ACT == 1) {
                    v0 = (v0 > 0.f) ? (v0 + 1.f) : __expf(v0);
                    v1 = (v1 > 0.f) ? (v1 + 1.f) : __expf(v1);
                } else if (ACT == 2) {
                    float c0 = v0 * v0 * v0;
                    v0 = 0.5f * v0 * (1.f + tanhf(0.7978845608028654f * (v0 + 0.044715f * c0)));
                    float c1 = v1 * v1 * v1;
                    v1 = 0.5f * v1 * (1.f + tanhf(0.7978845608028654f * (v1 + 0.044715f * c1)));
                }
                size_t base = (size_t)row * NC + col;
                if (OUT == 0) {
                    *reinterpret_cast<float2*>(Cf + base) = make_float2(v0, v1);
                } else {
                    __nv_bfloat16 h0 = __float2bfloat16(v0);
                    __nv_bfloat16 h1 = __float2bfloat16(v1);
                    __nv_bfloat16 l0 = __float2bfloat16(v0 - __bfloat162float(h0));
                    __nv_bfloat16 l1 = __float2bfloat16(v1 - __bfloat162float(h1));
                    uint32_t hp = ((uint32_t)__bfloat16_as_ushort(h1) << 16) | __bfloat16_as_ushort(h0);
                    uint32_t lp = ((uint32_t)__bfloat16_as_ushort(l1) << 16) | __bfloat16_as_ushort(l0);
                    *reinterpret_cast<uint32_t*>(Ch + base) = hp;
                    *reinterpret_cast<uint32_t*>(Cl + base) = lp;
                }
            }
        }
    }
}

// ============ K3: kv / ksum reduction over T ============
__global__ void kv_reduce_kernel(const float* __restrict__ pk,
                                 const float* __restrict__ v,
                                 float* __restrict__ kv,
                                 float* __restrict__ ksum) {
    int bh = blockIdx.x;
    int h  = bh % H_;
    int bj = bh / H_;
    int j  = bj % J_;
    int b  = bj / J_;
    int tid = threadIdx.x;
    int lane = tid & 31, w = tid >> 5;
    __shared__ float sp[4][32];
    __shared__ float sv[4][32];
    float acc[4] = {0.f, 0.f, 0.f, 0.f};
    float ks = 0.f;
    int tl = tid >> 6;
    int e  = tid & 63;
    for (int t0 = 0; t0 < T_; t0 += 4) {
        int t = t0 + tl;
        size_t base = (((size_t)(b * T_ + t) * J_) + j) * D_ + h * DH_;
        float val = (e < 32) ? pk[base + e] : v[base + e - 32];
        __syncthreads();
        if (e < 32) sp[tl][e] = val; else sv[tl][e - 32] = val;
        __syncthreads();
        #pragma unroll
        for (int tt = 0; tt < 4; tt++) {
            float vv = sv[tt][lane];
            #pragma unroll
            for (int c = 0; c < 4; c++)
                acc[c] += sp[tt][w + c * 8] * vv;
            if (w == 0) ks += sp[tt][lane];
        }
    }
    size_t ob = (size_t)bh * (DH_ * DH_);
    #pragma unroll
    for (int c = 0; c < 4; c++)
        kv[ob + (size_t)(w + c * 8) * 32 + lane] = acc[c];
    if (w == 0) ksum[(size_t)bh * 32 + lane] = ks;
}

// ============ K4: y = (pq @ kv) / (pq . ksum + EPS) -> bf16 hi/lo ============
__global__ void attn_apply_kernel(const float* __restrict__ pq,
                                  const float* __restrict__ kv,
                                  const float* __restrict__ ksum,
                                  __nv_bfloat16* __restrict__ yh,
                                  __nv_bfloat16* __restrict__ yl) {
    int bh = blockIdx.x;
    int h  = bh % H_;
    int bj = bh / H_;
    int j  = bj % J_;
    int b  = bj / J_;
    __shared__ float skv[DH_ * DH_];
    __shared__ float sks[DH_];
    int tid = threadIdx.x;
    for (int i = tid; i < DH_ * DH_; i += 256) skv[i] = kv[(size_t)bh * (DH_ * DH_) + i];
    if (tid < DH_) sks[tid] = ksum[(size_t)bh * DH_ + tid];
    __syncthreads();
    int lane = tid & 31, w = tid >> 5;
    for (int t = w; t < T_; t += 8) {
        size_t base = (((size_t)(b * T_ + t) * J_) + j) * D_ + h * DH_;
        float q = pq[base + lane];
        float den = q * sks[lane];
        #pragma unroll
        for (int o = 16; o; o >>= 1) den += __shfl_xor_sync(0xffffffffu, den, o);
        float num = 0.f;
        #pragma unroll
        for (int k = 0; k < 32; k++)
            num += __shfl_sync(0xffffffffu, q, k) * skv[k * 32 + lane];
        split_store(yh, yl, base + lane, num / (den + EPSF));
    }
}

// ============ K5: residual + LN2 -> bf16 hi/lo ============
__global__ void resid_kernel(const float* __restrict__ x,
                             const float* __restrict__ o_in,
                             const float* __restrict__ g2,
                             const float* __restrict__ b2,
                             __nv_bfloat16* __restrict__ uh,
                             __nv_bfloat16* __restrict__ ul) {
    __shared__ float sbuf[32];
    int row = blockIdx.x, i = threadIdx.x;
    const float* xr = x + (size_t)row * (D_ + 1);
    float o = o_in[(size_t)row * D_ + i];
    float so = block_reduce_sum(o * o, sbuf);
    float n  = fmaxf(sqrtf(so), EPSF);
    float z  = sinhf(n) * o / n;
    float m  = xr[1 + i] + z;
    float sm = block_reduce_sum(m * m, sbuf);
    float m0 = xr[0] + coshf(n);
    float mink = -m0 * m0 + sm;
    float inv  = rsqrtf(fmaxf(-mink, EPSF));
    float h0   = m0 * inv;
    float hs   = m * inv;
    float hn   = fmaxf(sqrtf(sm) * inv, EPSF);
    float u    = acoshf(fmaxf(h0, 1.0f + 1e-7f)) * hs / hn;
    float s1 = block_reduce_sum(u, sbuf);
    float s2 = block_reduce_sum(u * u, sbuf);
    float mean = s1 * (1.f / D_);
    float var  = s2 * (1.f / D_) - mean * mean;
    float uv = (u - mean) * rsqrtf(var + 1e-5f) * g2[i] + b2[i];
    split_store(uh, ul, (size_t)row * D_ + i, uv);
}

// ============ K6: out = expmap0(f) ============
__global__ void final_kernel(const float* __restrict__ f_in,
                             float* __restrict__ out) {
    __shared__ float sbuf[32];
    int row = blockIdx.x, i = threadIdx.x;
    float f = f_in[(size_t)row * D_ + i];
    float ss = block_reduce_sum(f * f, sbuf);
    float n  = fmaxf(sqrtf(ss), EPSF);
    float* orow = out + (size_t)row * (D_ + 1);
    orow[1 + i] = sinhf(n) * f / n;
    if (i == 0) orow[0] = coshf(n);
}

// ================= launch =================
extern "C" void kernel_launch(void* const* d_in, const int* /*in_sizes*/, int /*n_in*/,
                              void* d_out, int /*out_size*/) {
    const float* x     = (const float*)d_in[0];
    const float* g1    = (const float*)d_in[1];
    const float* beta1 = (const float*)d_in[2];
    const float* Wq    = (const float*)d_in[3];
    const float* Wk    = (const float*)d_in[4];
    const float* Wv    = (const float*)d_in[5];
    const float* Wo    = (const float*)d_in[6];
    const float* bq    = (const float*)d_in[7];
    const float* bk    = (const float*)d_in[8];
    const float* bv    = (const float*)d_in[9];
    const float* bo    = (const float*)d_in[10];
    const float* g2    = (const float*)d_in[11];
    const float* beta2 = (const float*)d_in[12];
    const float* W1    = (const float*)d_in[13];
    const float* bf1   = (const float*)d_in[14];
    const float* W2    = (const float*)d_in[15];
    const float* bf2   = (const float*)d_in[16];
    float* out = (float*)d_out;

    static bool attr_done = false;
    if (!attr_done) {
        cudaFuncSetAttribute(gemm_kernel<1,0>, cudaFuncAttributeMaxDynamicSharedMemorySize, GEMM_SMEM);
        cudaFuncSetAttribute(gemm_kernel<0,0>, cudaFuncAttributeMaxDynamicSharedMemorySize, GEMM_SMEM);
        cudaFuncSetAttribute(gemm_kernel<2,1>, cudaFuncAttributeMaxDynamicSharedMemorySize, GEMM_SMEM);
        attr_done = true;
    }

    __nv_bfloat16 *th, *tl, *hh, *hl;
    __nv_bfloat16 *wqh, *wql, *wkh, *wkl, *wvh, *wvl, *woh, *wol, *w1h, *w1l, *w2h, *w2l;
    float *q_, *k_, *v_, *kv_, *ks_;
    cudaGetSymbolAddress((void**)&th, g_th);   cudaGetSymbolAddress((void**)&tl, g_tl);
    cudaGetSymbolAddress((void**)&q_, g_q);    cudaGetSymbolAddress((void**)&k_, g_k);
    cudaGetSymbolAddress((void**)&v_, g_v);
    cudaGetSymbolAddress((void**)&hh, g_hh);   cudaGetSymbolAddress((void**)&hl, g_hl);
    cudaGetSymbolAddress((void**)&kv_, g_kv);  cudaGetSymbolAddress((void**)&ks_, g_ks);
    cudaGetSymbolAddress((void**)&wqh, g_wqh); cudaGetSymbolAddress((void**)&wql, g_wql);
    cudaGetSymbolAddress((void**)&wkh, g_wkh); cudaGetSymbolAddress((void**)&wkl, g_wkl);
    cudaGetSymbolAddress((void**)&wvh, g_wvh); cudaGetSymbolAddress((void**)&wvl, g_wvl);
    cudaGetSymbolAddress((void**)&woh, g_woh); cudaGetSymbolAddress((void**)&wol, g_wol);
    cudaGetSymbolAddress((void**)&w1h, g_w1h); cudaGetSymbolAddress((void**)&w1l, g_w1l);
    cudaGetSymbolAddress((void**)&w2h, g_w2h); cudaGetSymbolAddress((void**)&w2l, g_w2l);

    // 0. weight transpose+split (tiny)
    int nDD = D_ * D_, nDH = D_ * HID_;
    wsplit_kernel<<<(nDD + 255) / 256, 256>>>(Wq, wqh, wql, D_, D_);
    wsplit_kernel<<<(nDD + 255) / 256, 256>>>(Wk, wkh, wkl, D_, D_);
    wsplit_kernel<<<(nDD + 255) / 256, 256>>>(Wv, wvh, wvl, D_, D_);
    wsplit_kernel<<<(nDD + 255) / 256, 256>>>(Wo, woh, wol, D_, D_);
    wsplit_kernel<<<(nDH + 255) / 256, 256>>>(W1, w1h, w1l, D_, HID_);
    wsplit_kernel<<<(nDH + 255) / 256, 256>>>(W2, w2h, w2l, HID_, D_);

    // 1. pre: x -> t (bf16 split)
    pre_kernel<<<NTOK, 256>>>(x, g1, beta1, th, tl);

    // 2. QKV projections (HMMA)
    dim3 gD(D_ / 128, NTOK / 128);      // (2, 832)
    gemm_kernel<1,0><<<gD, 256, GEMM_SMEM>>>(th, tl, wqh, wql, bq, q_, nullptr, nullptr, D_, D_);
    gemm_kernel<1,0><<<gD, 256, GEMM_SMEM>>>(th, tl, wkh, wkl, bk, k_, nullptr, nullptr, D_, D_);
    gemm_kernel<0,0><<<gD, 256, GEMM_SMEM>>>(th, tl, wvh, wvl, bv, v_, nullptr, nullptr, D_, D_);

    // 3. linear attention
    kv_reduce_kernel<<<B_ * J_ * H_, 256>>>(k_, v_, kv_, ks_);
    attn_apply_kernel<<<B_ * J_ * H_, 256>>>(q_, kv_, ks_, th, tl);   // y -> th/tl

    // 4. output projection: o = y @ Wo + bo -> q_ (fp32)
    gemm_kernel<0,0><<<gD, 256, GEMM_SMEM>>>(th, tl, woh, wol, bo, q_, nullptr, nullptr, D_, D_);

    // 5. Lorentz residual + LN2 -> th/tl (u2)
    resid_kernel<<<NTOK, 256>>>(x, q_, g2, beta2, th, tl);

    // 6. FFN
    dim3 gH(HID_ / 128, NTOK / 128);    // (8, 832)
    gemm_kernel<2,1><<<gH, 256, GEMM_SMEM>>>(th, tl, w1h, w1l, bf1, nullptr, hh, hl, D_, HID_);
    gemm_kernel<0,0><<<gD, 256, GEMM_SMEM>>>(hh, hl, w2h, w2l, bf2, q_, nullptr, nullptr, HID_, D_);

    // 7. final expmap0 -> out
    final_kernel<<<NTOK, 256>>>(q_, out);
}